// round 1
// baseline (speedup 1.0000x reference)
#include <cuda_runtime.h>
#include <cuda_bf16.h>
#include <math_constants.h>

// Problem constants (fixed by the reference)
#define BATCH   2
#define SEQ     2048
#define CDIM    1024
#define NHEAD   16
#define HDIM    64
#define WINDOW  512
#define QKVDIM  (3 * CDIM)   // 3072

// Scratch (allocation-free rule: __device__ globals)
__device__ float g_qkv[BATCH * SEQ * QKVDIM];   // [B*T, 3C]
__device__ float g_y[BATCH * SEQ * CDIM];       // [B*T, C] attention output

// ---------------------------------------------------------------------------
// SGEMM: C[M,N] = A[M,K] @ B[K,N], all row-major, M%128==0, N%128==0, K%8==0
// 128x128 block tile, BK=8, 256 threads, 8x8 per-thread microtile
// ---------------------------------------------------------------------------
#define BM 128
#define BN 128
#define BK 8
#define TM 8
#define TN 8

__global__ __launch_bounds__(256, 2)
void sgemm_kernel(const float* __restrict__ A, const float* __restrict__ B,
                  float* __restrict__ C, int M, int N, int K)
{
    __shared__ float As[BK][BM];
    __shared__ float Bs[BK][BN];

    const int bx = blockIdx.x;   // N tile
    const int by = blockIdx.y;   // M tile
    const int tid = threadIdx.x; // 0..255
    const int tx = tid & 15;     // 0..15 -> N micro
    const int ty = tid >> 4;     // 0..15 -> M micro

    const float* Ag = A + (size_t)by * BM * K;
    const float* Bg = B + (size_t)bx * BN;

    // A tile load: 128 rows x 8 cols = 256 float4; thread -> row=tid>>1, col4=(tid&1)*4
    const int arow = tid >> 1;
    const int acol = (tid & 1) * 4;
    // B tile load: 8 rows x 128 cols = 256 float4; thread -> row=tid>>5, col=(tid&31)*4
    const int brow = tid >> 5;
    const int bcol = (tid & 31) * 4;

    float acc[TM][TN];
#pragma unroll
    for (int i = 0; i < TM; i++)
#pragma unroll
        for (int j = 0; j < TN; j++) acc[i][j] = 0.f;

    for (int k0 = 0; k0 < K; k0 += BK) {
        float4 av = *(const float4*)(Ag + (size_t)arow * K + k0 + acol);
        As[acol + 0][arow] = av.x;
        As[acol + 1][arow] = av.y;
        As[acol + 2][arow] = av.z;
        As[acol + 3][arow] = av.w;
        float4 bv = *(const float4*)(Bg + (size_t)(k0 + brow) * N + bcol);
        *(float4*)&Bs[brow][bcol] = bv;
        __syncthreads();

#pragma unroll
        for (int kk = 0; kk < BK; kk++) {
            float a[TM], b[TN];
            float4 a0 = *(const float4*)&As[kk][ty * TM];
            float4 a1 = *(const float4*)&As[kk][ty * TM + 4];
            a[0]=a0.x; a[1]=a0.y; a[2]=a0.z; a[3]=a0.w;
            a[4]=a1.x; a[5]=a1.y; a[6]=a1.z; a[7]=a1.w;
            float4 b0 = *(const float4*)&Bs[kk][tx * TN];
            float4 b1 = *(const float4*)&Bs[kk][tx * TN + 4];
            b[0]=b0.x; b[1]=b0.y; b[2]=b0.z; b[3]=b0.w;
            b[4]=b1.x; b[5]=b1.y; b[6]=b1.z; b[7]=b1.w;
#pragma unroll
            for (int i = 0; i < TM; i++)
#pragma unroll
                for (int j = 0; j < TN; j++)
                    acc[i][j] += a[i] * b[j];
        }
        __syncthreads();
    }

    float* Cg = C + (size_t)(by * BM + ty * TM) * N + bx * BN + tx * TN;
#pragma unroll
    for (int i = 0; i < TM; i++) {
        float4 v0 = {acc[i][0], acc[i][1], acc[i][2], acc[i][3]};
        float4 v1 = {acc[i][4], acc[i][5], acc[i][6], acc[i][7]};
        *(float4*)(Cg + (size_t)i * N + 0) = v0;
        *(float4*)(Cg + (size_t)i * N + 4) = v1;
    }
}

// ---------------------------------------------------------------------------
// Sliding-window attention: one thread per query row, flash-style online
// softmax. Block = 128 threads = 128 queries of one (b,h). K/V tiles of 64
// keys staged in shared memory; all threads broadcast-read the same key row.
// ---------------------------------------------------------------------------
#define QT 128
#define KT 64

__global__ __launch_bounds__(128)
void attn_kernel(const float* __restrict__ qkv, float* __restrict__ y)
{
    const int qtile = blockIdx.x;          // 0..SEQ/QT-1
    const int bh    = blockIdx.y;          // 0..B*H-1
    const int b = bh >> 4;                 // /NHEAD
    const int h = bh & 15;

    const int tid = threadIdx.x;           // 0..127
    const int q0  = qtile * QT;
    const int qi  = q0 + tid;              // global query index in [0,SEQ)

    const float* base = qkv + (size_t)b * SEQ * QKVDIM;

    // load q row into registers
    float q[HDIM];
    {
        const float* qrow = base + (size_t)qi * QKVDIM + h * HDIM;
#pragma unroll
        for (int d = 0; d < HDIM; d += 4) {
            float4 v = *(const float4*)(qrow + d);
            q[d] = v.x; q[d+1] = v.y; q[d+2] = v.z; q[d+3] = v.w;
        }
    }

    float o[HDIM];
#pragma unroll
    for (int d = 0; d < HDIM; d++) o[d] = 0.f;
    float m = -CUDART_INF_F;
    float l = 0.f;

    __shared__ float ks[KT][HDIM];
    __shared__ float vs[KT][HDIM];

    int jlo = q0 - WINDOW + 1;
    if (jlo < 0) jlo = 0;
    const int jt_start = jlo / KT;
    const int jt_end   = (q0 + QT - 1) / KT;

    const int lr = tid >> 4;          // 0..7
    const int lc = (tid & 15) * 4;    // 0..60

    for (int jt = jt_start; jt <= jt_end; jt++) {
        const int j0 = jt * KT;
        // stage K/V tile: 64 rows x 64 floats each
#pragma unroll
        for (int r = 0; r < 8; r++) {
            const int row = r * 8 + lr;
            const int j = j0 + row;
            const float* krow = base + (size_t)j * QKVDIM + CDIM + h * HDIM;
            *(float4*)&ks[row][lc] = *(const float4*)(krow + lc);
            *(float4*)&vs[row][lc] = *(const float4*)(krow + CDIM + lc);
        }
        __syncthreads();

        for (int jj = 0; jj < KT; jj++) {
            const int j = j0 + jj;
            const bool valid = (j <= qi) && (j > qi - WINDOW);
            if (valid) {
                float s = 0.f;
#pragma unroll
                for (int d = 0; d < HDIM; d += 4) {
                    float4 kv = *(const float4*)&ks[jj][d];
                    s += q[d] * kv.x + q[d+1] * kv.y + q[d+2] * kv.z + q[d+3] * kv.w;
                }
                s *= 0.125f; // 1/sqrt(64)

                if (s > m) {
                    const float corr = __expf(m - s);
                    m = s;
                    l *= corr;
#pragma unroll
                    for (int d = 0; d < HDIM; d++) o[d] *= corr;
                }
                const float p = __expf(s - m);
                l += p;
#pragma unroll
                for (int d = 0; d < HDIM; d += 4) {
                    float4 vv = *(const float4*)&vs[jj][d];
                    o[d]   += p * vv.x;
                    o[d+1] += p * vv.y;
                    o[d+2] += p * vv.z;
                    o[d+3] += p * vv.w;
                }
            }
        }
        __syncthreads();
    }

    const float inv = 1.f / l;
    float* yrow = y + ((size_t)b * SEQ + qi) * CDIM + h * HDIM;
#pragma unroll
    for (int d = 0; d < HDIM; d += 4) {
        float4 v = {o[d] * inv, o[d+1] * inv, o[d+2] * inv, o[d+3] * inv};
        *(float4*)(yrow + d) = v;
    }
}

// ---------------------------------------------------------------------------
extern "C" void kernel_launch(void* const* d_in, const int* in_sizes, int n_in,
                              void* d_out, int out_size)
{
    const float* x      = (const float*)d_in[0];   // [B,T,C]
    const float* w_attn = (const float*)d_in[1];   // [C,3C]
    const float* w_proj = (const float*)d_in[2];   // [C,C]
    float* out = (float*)d_out;                    // [B,T,C]

    float* qkv; cudaGetSymbolAddress((void**)&qkv, g_qkv);
    float* y;   cudaGetSymbolAddress((void**)&y,   g_y);

    const int M = BATCH * SEQ;  // 4096

    // 1) qkv = x @ w_attn   [4096,1024]@[1024,3072]
    {
        dim3 grid(QKVDIM / BN, M / BM);
        sgemm_kernel<<<grid, 256>>>(x, w_attn, qkv, M, QKVDIM, CDIM);
    }

    // 2) sliding-window attention -> y
    {
        dim3 grid(SEQ / QT, BATCH * NHEAD);
        attn_kernel<<<grid, 128>>>(qkv, y);
    }

    // 3) out = y @ w_proj   [4096,1024]@[1024,1024]
    {
        dim3 grid(CDIM / BN, M / BM);
        sgemm_kernel<<<grid, 256>>>(y, w_proj, out, M, CDIM, CDIM);
    }
}

// round 3
// speedup vs baseline: 1.6465x; 1.6465x over previous
#include <cuda_runtime.h>
#include <cuda_bf16.h>
#include <math_constants.h>

typedef unsigned int u32;
typedef unsigned long long u64;

// ---------------- problem constants ----------------
#define BATCH   2
#define SEQ     2048
#define CDIM    1024
#define NHEAD   16
#define HDIM    64
#define WINDOW  512
#define QKVDIM  3072
#define MROWS   (BATCH * SEQ)    // 4096

// ---------------- device scratch (allocation-free rule) ----------------
__device__ float         g_qkv[MROWS * QKVDIM];
__device__ __nv_bfloat16 g_xh[MROWS * CDIM];
__device__ __nv_bfloat16 g_xl[MROWS * CDIM];
__device__ __nv_bfloat16 g_yh[MROWS * CDIM];
__device__ __nv_bfloat16 g_yl[MROWS * CDIM];
__device__ __nv_bfloat16 g_wah[QKVDIM * CDIM];   // w_attn^T hi  [N=3072][K=1024]
__device__ __nv_bfloat16 g_wal[QKVDIM * CDIM];
__device__ __nv_bfloat16 g_wph[CDIM * CDIM];     // w_proj^T hi  [N=1024][K=1024]
__device__ __nv_bfloat16 g_wpl[CDIM * CDIM];

// ---------------- PTX helpers (base ISA only: sm_80-level) ----------------
__device__ __forceinline__ u32 smem_u32(const void* p) {
    u32 a;
    asm("{ .reg .u64 t; cvta.to.shared.u64 t, %1; cvt.u32.u64 %0, t; }" : "=r"(a) : "l"(p));
    return a;
}
__device__ __forceinline__ void ldm_x4(u32 addr, u32& r0, u32& r1, u32& r2, u32& r3) {
    asm volatile("ldmatrix.sync.aligned.m8n8.x4.shared.b16 {%0,%1,%2,%3}, [%4];"
                 : "=r"(r0), "=r"(r1), "=r"(r2), "=r"(r3) : "r"(addr));
}
__device__ __forceinline__ void mma_bf16(float* d, const u32* a, const u32* b) {
    asm volatile(
        "mma.sync.aligned.m16n8k16.row.col.f32.bf16.bf16.f32 "
        "{%0,%1,%2,%3}, {%4,%5,%6,%7}, {%8,%9}, {%0,%1,%2,%3};"
        : "+f"(d[0]), "+f"(d[1]), "+f"(d[2]), "+f"(d[3])
        : "r"(a[0]), "r"(a[1]), "r"(a[2]), "r"(a[3]), "r"(b[0]), "r"(b[1]));
}

// ---------------- pre-pass kernels ----------------
__global__ __launch_bounds__(256) void split_kernel(
    const float* __restrict__ A, __nv_bfloat16* __restrict__ hi, __nv_bfloat16* __restrict__ lo, int n)
{
    int i = (blockIdx.x * 256 + threadIdx.x) * 4;
    if (i >= n) return;
    float4 v = *(const float4*)(A + i);
    __nv_bfloat16 h0 = __float2bfloat16(v.x), h1 = __float2bfloat16(v.y);
    __nv_bfloat16 h2 = __float2bfloat16(v.z), h3 = __float2bfloat16(v.w);
    __nv_bfloat16 l0 = __float2bfloat16(v.x - __bfloat162float(h0));
    __nv_bfloat16 l1 = __float2bfloat16(v.y - __bfloat162float(h1));
    __nv_bfloat16 l2 = __float2bfloat16(v.z - __bfloat162float(h2));
    __nv_bfloat16 l3 = __float2bfloat16(v.w - __bfloat162float(h3));
    *(__nv_bfloat162*)(hi + i)     = __nv_bfloat162(h0, h1);
    *(__nv_bfloat162*)(hi + i + 2) = __nv_bfloat162(h2, h3);
    *(__nv_bfloat162*)(lo + i)     = __nv_bfloat162(l0, l1);
    *(__nv_bfloat162*)(lo + i + 2) = __nv_bfloat162(l2, l3);
}

__global__ __launch_bounds__(256) void transpose_split_kernel(
    const float* __restrict__ W, __nv_bfloat16* __restrict__ Thi, __nv_bfloat16* __restrict__ Tlo,
    int K, int N)
{
    __shared__ float tile[32][33];
    const int n0 = blockIdx.x * 32, k0 = blockIdx.y * 32;
    const int tx = threadIdx.x, ty = threadIdx.y; // 32 x 8
#pragma unroll
    for (int r = 0; r < 32; r += 8)
        tile[ty + r][tx] = W[(size_t)(k0 + ty + r) * N + n0 + tx];
    __syncthreads();
#pragma unroll
    for (int r = 0; r < 32; r += 8) {
        float v = tile[tx][ty + r];
        __nv_bfloat16 h = __float2bfloat16(v);
        __nv_bfloat16 l = __float2bfloat16(v - __bfloat162float(h));
        size_t o = (size_t)(n0 + ty + r) * K + k0 + tx;
        Thi[o] = h;
        Tlo[o] = l;
    }
}

// ---------------- bf16x3 GEMM on HMMA (mma.sync m16n8k16) ----------------
// C[M,N] = A[M,K] @ B[N,K]^T via Ah*Bh + Ah*Bl + Al*Bh
// Block tile 128x128, BK=32, 8 warps: wm = warp>>1 (4 rows of 32), wn = warp&1 (2 cols of 64)
#define SPAD 40   // bf16 row stride in smem (80B -> conflict-free ldmatrix)

__global__ __launch_bounds__(256, 2)
void gemm_bf16x3(const __nv_bfloat16* __restrict__ Ah, const __nv_bfloat16* __restrict__ Al,
                 const __nv_bfloat16* __restrict__ Bh, const __nv_bfloat16* __restrict__ Bl,
                 float* __restrict__ C, int M, int N, int K)
{
    __shared__ __nv_bfloat16 sAh[128][SPAD];
    __shared__ __nv_bfloat16 sAl[128][SPAD];
    __shared__ __nv_bfloat16 sBh[128][SPAD];
    __shared__ __nv_bfloat16 sBl[128][SPAD];

    const int tid = threadIdx.x;
    const int warp = tid >> 5, ln = tid & 31;
    const int wm = warp >> 1, wn = warp & 1;
    const int bx = blockIdx.x, by = blockIdx.y;

    const __nv_bfloat16* gAh = Ah + (size_t)by * 128 * K;
    const __nv_bfloat16* gAl = Al + (size_t)by * 128 * K;
    const __nv_bfloat16* gBh = Bh + (size_t)bx * 128 * K;
    const __nv_bfloat16* gBl = Bl + (size_t)bx * 128 * K;

    float acc[2][8][4];
#pragma unroll
    for (int mt = 0; mt < 2; mt++)
#pragma unroll
        for (int nt = 0; nt < 8; nt++)
#pragma unroll
            for (int r = 0; r < 4; r++) acc[mt][nt][r] = 0.f;

    const u32 sA_h = smem_u32(&sAh[0][0]);
    const u32 sA_l = smem_u32(&sAl[0][0]);
    const u32 sB_h = smem_u32(&sBh[0][0]);
    const u32 sB_l = smem_u32(&sBl[0][0]);

    // ldmatrix lane addressing (x4, 16x16 tiles)
    const int a_r = (ln & 7) + ((ln >> 3) & 1) * 8;   // row within 16
    const int a_k = (ln >> 4) * 8;                     // k-half
    const int b_p = (ln >> 4);                         // n-subtile within pair
    const int b_r = (ln & 7);
    const int b_k = ((ln >> 3) & 1) * 8;

    const int lrow = tid >> 1;             // load row 0..127
    const int lc0  = (tid & 1);            // chunk 0..1 (then 2..3)

    for (int k0 = 0; k0 < K; k0 += 32) {
#pragma unroll
        for (int it = 0; it < 2; it++) {
            const int c8 = lc0 + 2 * it;
            const size_t go = (size_t)lrow * K + k0 + c8 * 8;
            *(uint4*)&sAh[lrow][c8 * 8] = *(const uint4*)(gAh + go);
            *(uint4*)&sAl[lrow][c8 * 8] = *(const uint4*)(gAl + go);
            *(uint4*)&sBh[lrow][c8 * 8] = *(const uint4*)(gBh + go);
            *(uint4*)&sBl[lrow][c8 * 8] = *(const uint4*)(gBl + go);
        }
        __syncthreads();

#pragma unroll
        for (int ks = 0; ks < 2; ks++) {
            u32 afh[2][4], afl[2][4];
#pragma unroll
            for (int mt = 0; mt < 2; mt++) {
                const int row = wm * 32 + mt * 16 + a_r;
                const u32 off = (u32)(row * (SPAD * 2) + (ks * 16 + a_k) * 2);
                ldm_x4(sA_h + off, afh[mt][0], afh[mt][1], afh[mt][2], afh[mt][3]);
                ldm_x4(sA_l + off, afl[mt][0], afl[mt][1], afl[mt][2], afl[mt][3]);
            }
#pragma unroll
            for (int bq = 0; bq < 4; bq++) {
                const int nrow = wn * 64 + (bq * 2 + b_p) * 8 + b_r;
                const u32 off = (u32)(nrow * (SPAD * 2) + (ks * 16 + b_k) * 2);
                u32 h0, h1, h2, h3, l0, l1, l2, l3;
                ldm_x4(sB_h + off, h0, h1, h2, h3);
                ldm_x4(sB_l + off, l0, l1, l2, l3);
                u32 bh0[2] = {h0, h1}, bh1[2] = {h2, h3};
                u32 bl0[2] = {l0, l1}, bl1[2] = {l2, l3};
#pragma unroll
                for (int mt = 0; mt < 2; mt++) {
                    mma_bf16(acc[mt][2 * bq + 0], afh[mt], bh0);
                    mma_bf16(acc[mt][2 * bq + 1], afh[mt], bh1);
                    mma_bf16(acc[mt][2 * bq + 0], afh[mt], bl0);
                    mma_bf16(acc[mt][2 * bq + 1], afh[mt], bl1);
                    mma_bf16(acc[mt][2 * bq + 0], afl[mt], bh0);
                    mma_bf16(acc[mt][2 * bq + 1], afl[mt], bh1);
                }
            }
        }
        __syncthreads();
    }

    // epilogue: c0,c1 -> (m = ln>>2, n = (ln&3)*2), c2,c3 -> m+8
    const int em = ln >> 2, en = (ln & 3) * 2;
#pragma unroll
    for (int mt = 0; mt < 2; mt++) {
        const size_t row0 = (size_t)(by * 128 + wm * 32 + mt * 16 + em);
#pragma unroll
        for (int nt = 0; nt < 8; nt++) {
            const size_t col = (size_t)(bx * 128 + wn * 64 + nt * 8 + en);
            float2 v0 = {acc[mt][nt][0], acc[mt][nt][1]};
            float2 v1 = {acc[mt][nt][2], acc[mt][nt][3]};
            *(float2*)(C + row0 * N + col)       = v0;
            *(float2*)(C + (row0 + 8) * N + col) = v1;
        }
    }
}

// ---------------- sliding-window attention (fp32, bf16 hi/lo out) ----------------
#define QT 128
#define KT 64

__global__ __launch_bounds__(128) void attn_kernel(
    const float* __restrict__ qkv,
    __nv_bfloat16* __restrict__ yh, __nv_bfloat16* __restrict__ yl)
{
    const int qtile = blockIdx.x;
    const int bh = blockIdx.y;
    const int b = bh >> 4;
    const int h = bh & 15;

    const int tid = threadIdx.x;
    const int q0 = qtile * QT;
    const int qi = q0 + tid;

    const float* base = qkv + (size_t)b * SEQ * QKVDIM;

    float q[HDIM], o[HDIM];
    {
        const float* qrow = base + (size_t)qi * QKVDIM + h * HDIM;
#pragma unroll
        for (int d = 0; d < HDIM; d += 4) {
            float4 v = *(const float4*)(qrow + d);
            q[d] = v.x; q[d+1] = v.y; q[d+2] = v.z; q[d+3] = v.w;
        }
    }
#pragma unroll
    for (int d = 0; d < HDIM; d++) o[d] = 0.f;
    float m = -CUDART_INF_F;
    float l = 0.f;

    __shared__ float ks[KT][HDIM];
    __shared__ float vs[KT][HDIM];

    int jlo = q0 - WINDOW + 1;
    if (jlo < 0) jlo = 0;
    const int jt_start = jlo / KT;
    const int jt_end = (q0 + QT - 1) / KT;

    const int lr = tid >> 4;
    const int lc = (tid & 15) * 4;

    for (int jt = jt_start; jt <= jt_end; jt++) {
        const int j0 = jt * KT;
#pragma unroll
        for (int r = 0; r < 8; r++) {
            const int row = r * 8 + lr;
            const float* krow = base + (size_t)(j0 + row) * QKVDIM + CDIM + h * HDIM;
            *(float4*)&ks[row][lc] = *(const float4*)(krow + lc);
            *(float4*)&vs[row][lc] = *(const float4*)(krow + CDIM + lc);
        }
        __syncthreads();

        // tile fully valid for every thread of this block?
        const bool full = (j0 + KT - 1 <= q0) && (j0 >= q0 + QT - WINDOW);

        if (full) {
            for (int jj = 0; jj < KT; jj++) {
                float s = 0.f;
#pragma unroll
                for (int d = 0; d < HDIM; d += 4) {
                    float4 kv = *(const float4*)&ks[jj][d];
                    s += q[d] * kv.x + q[d+1] * kv.y + q[d+2] * kv.z + q[d+3] * kv.w;
                }
                s *= 0.125f;
                if (s > m) {
                    const float corr = __expf(m - s);
                    m = s;
                    l *= corr;
#pragma unroll
                    for (int d = 0; d < HDIM; d++) o[d] *= corr;
                }
                const float p = __expf(s - m);
                l += p;
#pragma unroll
                for (int d = 0; d < HDIM; d += 4) {
                    float4 vv = *(const float4*)&vs[jj][d];
                    o[d]   += p * vv.x;
                    o[d+1] += p * vv.y;
                    o[d+2] += p * vv.z;
                    o[d+3] += p * vv.w;
                }
            }
        } else {
            for (int jj = 0; jj < KT; jj++) {
                const int j = j0 + jj;
                const bool valid = (j <= qi) && (j > qi - WINDOW);
                if (valid) {
                    float s = 0.f;
#pragma unroll
                    for (int d = 0; d < HDIM; d += 4) {
                        float4 kv = *(const float4*)&ks[jj][d];
                        s += q[d] * kv.x + q[d+1] * kv.y + q[d+2] * kv.z + q[d+3] * kv.w;
                    }
                    s *= 0.125f;
                    if (s > m) {
                        const float corr = __expf(m - s);
                        m = s;
                        l *= corr;
#pragma unroll
                        for (int d = 0; d < HDIM; d++) o[d] *= corr;
                    }
                    const float p = __expf(s - m);
                    l += p;
#pragma unroll
                    for (int d = 0; d < HDIM; d += 4) {
                        float4 vv = *(const float4*)&vs[jj][d];
                        o[d]   += p * vv.x;
                        o[d+1] += p * vv.y;
                        o[d+2] += p * vv.z;
                        o[d+3] += p * vv.w;
                    }
                }
            }
        }
        __syncthreads();
    }

    const float inv = 1.f / l;
    __nv_bfloat16 hb[HDIM], lb[HDIM];
#pragma unroll
    for (int d = 0; d < HDIM; d++) {
        float f = o[d] * inv;
        __nv_bfloat16 hv = __float2bfloat16(f);
        hb[d] = hv;
        lb[d] = __float2bfloat16(f - __bfloat162float(hv));
    }
    const size_t orow = ((size_t)b * SEQ + qi) * CDIM + h * HDIM;
#pragma unroll
    for (int j = 0; j < 8; j++) {
        *(uint4*)(yh + orow + j * 8) = ((const uint4*)hb)[j];
        *(uint4*)(yl + orow + j * 8) = ((const uint4*)lb)[j];
    }
}

// ---------------- launch ----------------
extern "C" void kernel_launch(void* const* d_in, const int* in_sizes, int n_in,
                              void* d_out, int out_size)
{
    const float* x      = (const float*)d_in[0];   // [B,T,C]
    const float* w_attn = (const float*)d_in[1];   // [C,3C]
    const float* w_proj = (const float*)d_in[2];   // [C,C]
    float* out = (float*)d_out;

    float* qkv;
    __nv_bfloat16 *xh, *xl, *yh, *yl, *wah, *wal, *wph, *wpl;
    cudaGetSymbolAddress((void**)&qkv, g_qkv);
    cudaGetSymbolAddress((void**)&xh, g_xh);
    cudaGetSymbolAddress((void**)&xl, g_xl);
    cudaGetSymbolAddress((void**)&yh, g_yh);
    cudaGetSymbolAddress((void**)&yl, g_yl);
    cudaGetSymbolAddress((void**)&wah, g_wah);
    cudaGetSymbolAddress((void**)&wal, g_wal);
    cudaGetSymbolAddress((void**)&wph, g_wph);
    cudaGetSymbolAddress((void**)&wpl, g_wpl);

    // pre-passes
    {
        int n = MROWS * CDIM;
        split_kernel<<<n / (256 * 4), 256>>>(x, xh, xl, n);
        dim3 blk(32, 8);
        transpose_split_kernel<<<dim3(QKVDIM / 32, CDIM / 32), blk>>>(w_attn, wah, wal, CDIM, QKVDIM);
        transpose_split_kernel<<<dim3(CDIM / 32, CDIM / 32), blk>>>(w_proj, wph, wpl, CDIM, CDIM);
    }

    // GEMM1: qkv[4096,3072] = x @ w_attn
    gemm_bf16x3<<<dim3(QKVDIM / 128, MROWS / 128), 256>>>(xh, xl, wah, wal, qkv, MROWS, QKVDIM, CDIM);

    // attention -> y (bf16 hi/lo)
    attn_kernel<<<dim3(SEQ / QT, BATCH * NHEAD), 128>>>(qkv, yh, yl);

    // GEMM2: out[4096,1024] = y @ w_proj
    gemm_bf16x3<<<dim3(CDIM / 128, MROWS / 128), 256>>>(yh, yl, wph, wpl, out, MROWS, CDIM, CDIM);
}